// round 5
// baseline (speedup 1.0000x reference)
#include <cuda_runtime.h>
#include <math.h>

// ---------------- problem constants ----------------
#define Bc    8
#define Pc    16
#define Vc    32
#define Dc    686          // (20-2)*(39-1)+2
#define BPc   128          // B*P
#define NPCc  16384
#define NNSc  8192
#define NOUTc 8192
#define PDc   10976        // P*D

// ---------------- output offsets (tuple order, flattened) ----------------
#define OFF_OVERLAP 0                         // (B,P,P,1)     2048
#define OFF_DIST    2048                      // (B,P,NPC,1)   2097152
#define OFF_X       2099200                   // (B,P,D,3)     263424
#define OFF_SURFD   2362624                   // (B,P,P*D,1)   1404928
#define OFF_SURFP   3767552                   // (B,P*D,3)     263424
#define OFF_NS      4030976                   // (B,P,NNS,1)   1048576
#define OFF_OUT     5079552                   // (B,P,NOUT,1)  1048576
// total = 6128128

// ---------------- persistent device scratch ----------------
__device__ float  g_dirs[Dc * 3];
__device__ float  g_lv[BPc * 96];     // centered verts, [bp][coord(0..2)][v(0..31)]
__device__ float  g_tr[BPc * 3];      // mean (translation)
__device__ float  g_pe[BPc];
__device__ float  g_ipe[BPc];
__device__ float  g_scale[BPc];
__device__ float  g_nrml[BPc * Dc * 3];

// ---------------- core: soft support function ----------------
// z[v] = dot(vert_v, u);  h = (sum clip(max(z,0)/zmax)^pe)^(1/pe)
// NOTE: fmax(fmax(z,0)*k, 1e-30) == fmax(z*k, 1e-30) because k = 1/zmax > 0.
__device__ __forceinline__ float spt_core(
    const float4* __restrict__ sv,
    float pe, float ipe, float ux, float uy, float uz,
    float z[Vc], float& zmax_out)
{
    float zm = -1e30f;
#pragma unroll
    for (int v = 0; v < Vc; v++) {
        float4 w = sv[v];
        float zz = fmaf(w.x, ux, fmaf(w.y, uy, w.z * uz));
        z[v] = zz;
        zm = fmaxf(zm, zz);
    }
    zm = fminf(fmaxf(zm, 1e-30f), 1e30f);
    float k = 1.0f / zm;
    float sum = 0.0f;
#pragma unroll
    for (int v = 0; v < Vc; v++) {
        float t = fmaxf(z[v] * k, 1e-30f);
        sum += __powf(t, pe);
    }
    zmax_out = zm;
    return __powf(sum, ipe);
}

// h_out = clip(h * zmax, -1e30, 1e30)
__device__ __forceinline__ float h_clip(float h, float zm) {
    return fminf(fmaxf(h * zm, -1e30f), 1e30f);
}

// load one bp's vertex set into a float4 shared array (call with tid, then sync)
__device__ __forceinline__ void load_verts(float4* sv, int bp, int tid) {
    if (tid < Vc) {
        sv[tid] = make_float4(g_lv[bp * 96 +  0 + tid],
                              g_lv[bp * 96 + 32 + tid],
                              g_lv[bp * 96 + 64 + tid], 0.0f);
    }
}

// ---------------- kernel: directions (matches numpy linspace/cos in double) ----------------
__global__ void k_dirs() {
    int idx = blockIdx.x * blockDim.x + threadIdx.x;
    if (idx >= Dc) return;
    const double PI = 3.14159265358979323846;
    int i, j;
    if (idx < 684)      { i = idx / 38 + 1; j = idx % 38; }
    else if (idx == 684){ i = 0;  j = 0; }
    else                { i = 19; j = 0; }
    // numpy linspace: arange(n)*step + start, endpoint overwritten exactly
    double th1 = (i == 19) ? (PI / 2.0) : (-PI / 2.0 + (PI / 19.0) * (double)i);
    double th2 = -PI + (PI / 19.0) * (double)j;   // j <= 37, endpoint unused
    double c1 = cos(th1), s1 = sin(th1);
    double c2 = cos(th2), s2 = sin(th2);
    g_dirs[idx * 3 + 0] = (float)(c1 * c2);
    g_dirs[idx * 3 + 1] = (float)(c1 * s2);
    g_dirs[idx * 3 + 2] = (float)s1;
}

// ---------------- kernel: prep (mean, center, pe) ----------------
__global__ void k_prep(const float* __restrict__ verts, const float* __restrict__ smooth) {
    int bp = blockIdx.x;
    int v  = threadIdx.x;   // 32 threads
    float x = verts[(bp * Vc + v) * 3 + 0];
    float y = verts[(bp * Vc + v) * 3 + 1];
    float z = verts[(bp * Vc + v) * 3 + 2];
    float sx = x, sy = y, sz = z;
#pragma unroll
    for (int o = 16; o; o >>= 1) {
        sx += __shfl_xor_sync(0xffffffffu, sx, o);
        sy += __shfl_xor_sync(0xffffffffu, sy, o);
        sz += __shfl_xor_sync(0xffffffffu, sz, o);
    }
    float mx = sx * (1.0f / 32.0f);
    float my = sy * (1.0f / 32.0f);
    float mz = sz * (1.0f / 32.0f);
    g_lv[bp * 96 +  0 + v] = x - mx;
    g_lv[bp * 96 + 32 + v] = y - my;
    g_lv[bp * 96 + 64 + v] = z - mz;
    if (v == 0) {
        g_tr[bp * 3 + 0] = mx;
        g_tr[bp * 3 + 1] = my;
        g_tr[bp * 3 + 2] = mz;
        float pe = smooth[bp];
        g_pe[bp]  = pe;
        g_ipe[bp] = 1.0f / pe;
    }
}

// ---------------- kernel: support along DIRS + x output + scale ----------------
// 256 threads/block; each thread processes 3 directions (686 <= 3*256).
__global__ void __launch_bounds__(256) k_support(float* __restrict__ out) {
    __shared__ float4 sv[Vc];
    __shared__ float sconst[2];        // pe, ipe
    __shared__ float red[8];
    int bp  = blockIdx.x;
    int tid = threadIdx.x;
    load_verts(sv, bp, tid);
    if (tid == 0) { sconst[0] = g_pe[bp]; sconst[1] = g_ipe[bp]; }
    __syncthreads();

    float hmax = -1e30f;
    for (int d = tid; d < Dc; d += 256) {
        float ux = g_dirs[d * 3 + 0];
        float uy = g_dirs[d * 3 + 1];
        float uz = g_dirs[d * 3 + 2];
        float z[Vc], zm;
        float h = spt_core(sv, sconst[0], sconst[1], ux, uy, uz, z, zm);
        hmax = fmaxf(hmax, h_clip(h, zm));
        out[OFF_X + (bp * Dc + d) * 3 + 0] = ux;
        out[OFF_X + (bp * Dc + d) * 3 + 1] = uy;
        out[OFF_X + (bp * Dc + d) * 3 + 2] = uz;
    }
    // block max-reduce -> scale
    float m = hmax;
#pragma unroll
    for (int o = 16; o; o >>= 1) m = fmaxf(m, __shfl_xor_sync(0xffffffffu, m, o));
    if ((tid & 31) == 0) red[tid >> 5] = m;
    __syncthreads();
    if (tid == 0) {
        float mm = red[0];
#pragma unroll
        for (int w = 1; w < 8; w++) mm = fmaxf(mm, red[w]);
        g_scale[bp] = fminf(fmaxf(mm, 1e-10f), 10.0f);
    }
}

// ---------------- kernel: overlap (one block per batch) ----------------
__global__ void __launch_bounds__(256) k_overlap(float* __restrict__ out) {
    __shared__ float4 sv[Pc * Vc];
    __shared__ float st[Pc * 3];
    __shared__ float spe[Pc], sipe[Pc];
    __shared__ float sh[Pc * Pc];
    int b   = blockIdx.x;
    int tid = threadIdx.x;   // 256
    {
        int p = tid >> 4, v2 = (tid & 15) * 2;
        // each thread loads 2 vertices of hull p
        sv[p * Vc + v2 + 0] = make_float4(g_lv[(b * Pc + p) * 96 +  0 + v2],
                                          g_lv[(b * Pc + p) * 96 + 32 + v2],
                                          g_lv[(b * Pc + p) * 96 + 64 + v2], 0.0f);
        sv[p * Vc + v2 + 1] = make_float4(g_lv[(b * Pc + p) * 96 +  0 + v2 + 1],
                                          g_lv[(b * Pc + p) * 96 + 32 + v2 + 1],
                                          g_lv[(b * Pc + p) * 96 + 64 + v2 + 1], 0.0f);
    }
    if (tid < Pc * 3) st[tid] = g_tr[b * Pc * 3 + tid];
    if (tid < Pc) { spe[tid] = g_pe[b * Pc + tid]; sipe[tid] = g_ipe[b * Pc + tid]; }
    __syncthreads();

    int i = tid >> 4, j = tid & 15;
    float dx = st[j * 3 + 0] - st[i * 3 + 0];
    float dy = st[j * 3 + 1] - st[i * 3 + 1];
    float dz = st[j * 3 + 2] - st[i * 3 + 2];
    float ss = dx * dx + dy * dy + dz * dz;
    ss = fminf(fmaxf(ss, 1e-20f), 1e20f);
    float dn = sqrtf(ss);
    float ux, uy, uz;
    if (i == j) { ux = 1.0f; uy = 0.0f; uz = 0.0f; }
    else        { ux = dx / dn; uy = dy / dn; uz = dz / dn; }

    float z[Vc], zm;
    float h = spt_core(&sv[i * Vc], spe[i], sipe[i], ux, uy, uz, z, zm);
    sh[tid] = h_clip(h, zm);
    __syncthreads();

    float sep = dn - sh[i * 16 + j] - sh[j * 16 + i];
    float ov = fmaxf(-sep, 0.0f);
    if (i == j) ov = 0.0f;
    out[OFF_OVERLAP + b * 256 + i * 16 + j] = ov;
}

// ---------------- kernel: surface points + normals ----------------
// grid: (ceil(Dc/256), BPc), 256 threads
__global__ void __launch_bounds__(256) k_surf(float* __restrict__ out) {
    __shared__ float4 sv[Vc];
    __shared__ float sconst[6];   // tx,ty,tz,pe,ipe,scale
    int bp  = blockIdx.y;
    int tid = threadIdx.x;
    load_verts(sv, bp, tid);
    if (tid == 0) {
        sconst[0] = g_tr[bp * 3 + 0];
        sconst[1] = g_tr[bp * 3 + 1];
        sconst[2] = g_tr[bp * 3 + 2];
        sconst[3] = g_pe[bp];
        sconst[4] = g_ipe[bp];
        sconst[5] = g_scale[bp];
    }
    __syncthreads();
    int d = blockIdx.x * 256 + tid;
    if (d >= Dc) return;

    float sc = sconst[5];
    float dxr = g_dirs[d * 3 + 0];
    float dyr = g_dirs[d * 3 + 1];
    float dzr = g_dirs[d * 3 + 2];
    // pts = dirs*scale + trans; local = pts - trans  (replicate reference rounding)
    float px = dxr * sc + sconst[0];
    float py = dyr * sc + sconst[1];
    float pz = dzr * sc + sconst[2];
    float lx = px - sconst[0];
    float ly = py - sconst[1];
    float lz = pz - sconst[2];
    float ss = lx * lx + ly * ly + lz * lz;
    ss = fminf(fmaxf(ss, 1e-40f), 1e40f);
    float nrm = sqrtf(ss);
    float ux = lx / nrm, uy = ly / nrm, uz = lz / nrm;

    float pe = sconst[3];
    float z[Vc], zm;
    float h = spt_core(sv, pe, sconst[4], ux, uy, uz, z, zm);
    float s = fminf(fmaxf(h, 1e-30f), 1e30f);
    float rins = 1.0f / s;
    float k = 1.0f / zm;
    float pem1 = pe - 1.0f;
    float ax = 0.0f, ay = 0.0f, az = 0.0f;
#pragma unroll
    for (int v = 0; v < Vc; v++) {
        float t = fmaxf(z[v] * k, 1e-30f);
        float r = t * rins;
        float dh = fminf(fmaxf(__powf(r, pem1), 1e-30f), 1e30f);
        float4 w = sv[v];
        ax = fmaf(dh, w.x, ax);
        ay = fmaf(dh, w.y, ay);
        az = fmaf(dh, w.z, az);
    }
    int base = OFF_SURFP + (bp * Dc + d) * 3;
    out[base + 0] = ax + sconst[0];
    out[base + 1] = ay + sconst[1];
    out[base + 2] = az + sconst[2];
    g_nrml[(bp * Dc + d) * 3 + 0] = ux;
    g_nrml[(bp * Dc + d) * 3 + 1] = uy;
    g_nrml[(bp * Dc + d) * 3 + 2] = uz;
}

// ---------------- kernel: generic point-distance ----------------
__global__ void __launch_bounds__(256) k_dist(const float* __restrict__ pts, int N,
                                              float* __restrict__ out, int outoff) {
    __shared__ float4 sv[Vc];
    __shared__ float sconst[5];   // tx,ty,tz,pe,ipe
    int bp  = blockIdx.y;
    int tid = threadIdx.x;
    load_verts(sv, bp, tid);
    if (tid == 0) {
        sconst[0] = g_tr[bp * 3 + 0];
        sconst[1] = g_tr[bp * 3 + 1];
        sconst[2] = g_tr[bp * 3 + 2];
        sconst[3] = g_pe[bp];
        sconst[4] = g_ipe[bp];
    }
    __syncthreads();
    int q = blockIdx.x * blockDim.x + tid;
    if (q >= N) return;
    int b = bp >> 4;
    float px = pts[(b * N + q) * 3 + 0];
    float py = pts[(b * N + q) * 3 + 1];
    float pz = pts[(b * N + q) * 3 + 2];
    float lx = px - sconst[0];
    float ly = py - sconst[1];
    float lz = pz - sconst[2];
    float ss = lx * lx + ly * ly + lz * lz;
    ss = fminf(fmaxf(ss, 1e-40f), 1e40f);
    float nrm = sqrtf(ss);
    float ux = lx / nrm, uy = ly / nrm, uz = lz / nrm;
    float z[Vc], zm;
    float h = spt_core(sv, sconst[3], sconst[4], ux, uy, uz, z, zm);
    out[outoff + bp * N + q] = nrm - h_clip(h, zm);
}

// ---------------- kernel: surf_distance (with normal filter + diagonal) ----------------
__global__ void __launch_bounds__(256) k_sdist(const float* __restrict__ outro,
                                               float* __restrict__ out) {
    __shared__ float4 sv[Vc];
    __shared__ float st[Pc * 3];
    __shared__ float sconst[5];
    int bp  = blockIdx.y;
    int b   = bp >> 4;
    int i   = bp & 15;
    int tid = threadIdx.x;
    load_verts(sv, bp, tid);
    if (tid < Pc * 3) st[tid] = g_tr[b * Pc * 3 + tid];
    if (tid == 0) {
        sconst[0] = g_tr[bp * 3 + 0];
        sconst[1] = g_tr[bp * 3 + 1];
        sconst[2] = g_tr[bp * 3 + 2];
        sconst[3] = g_pe[bp];
        sconst[4] = g_ipe[bp];
    }
    __syncthreads();
    int n = blockIdx.x * blockDim.x + tid;
    if (n >= PDc) return;
    int j  = n / Dc;
    int dd = n - j * Dc;

    float res = 100.0f;
    bool compute = (i != j);
    if (compute) {
        float nx = g_nrml[(bp * Dc + dd) * 3 + 0];
        float ny = g_nrml[(bp * Dc + dd) * 3 + 1];
        float nz = g_nrml[(bp * Dc + dd) * 3 + 2];
        float ltx = st[j * 3 + 0] - sconst[0];
        float lty = st[j * 3 + 1] - sconst[1];
        float ltz = st[j * 3 + 2] - sconst[2];
        float nf = ltx * nx + lty * ny + ltz * nz;
        compute = !(nf < 0.0f);
    }
    if (compute) {
        float px = outro[OFF_SURFP + (b * PDc + n) * 3 + 0];
        float py = outro[OFF_SURFP + (b * PDc + n) * 3 + 1];
        float pz = outro[OFF_SURFP + (b * PDc + n) * 3 + 2];
        float lx = px - sconst[0];
        float ly = py - sconst[1];
        float lz = pz - sconst[2];
        float ss = lx * lx + ly * ly + lz * lz;
        ss = fminf(fmaxf(ss, 1e-40f), 1e40f);
        float nrm = sqrtf(ss);
        float ux = lx / nrm, uy = ly / nrm, uz = lz / nrm;
        float z[Vc], zm;
        float h = spt_core(sv, sconst[3], sconst[4], ux, uy, uz, z, zm);
        res = nrm - h_clip(h, zm);
    }
    out[OFF_SURFD + bp * PDc + n] = res;
}

// ---------------- launch ----------------
extern "C" void kernel_launch(void* const* d_in, const int* in_sizes, int n_in,
                              void* d_out, int out_size) {
    const float* verts  = (const float*)d_in[0];   // (B,P,V,3)
    const float* smooth = (const float*)d_in[1];   // (B,P)
    const float* pc     = (const float*)d_in[2];   // (B,NPC,3)
    const float* ns     = (const float*)d_in[3];   // (B,NNS,3)
    const float* op     = (const float*)d_in[4];   // (B,NOUT,3)
    float* out = (float*)d_out;

    k_dirs<<<3, 256>>>();
    k_prep<<<BPc, 32>>>(verts, smooth);
    k_support<<<BPc, 256>>>(out);
    k_overlap<<<Bc, 256>>>(out);
    k_surf<<<dim3((Dc + 255) / 256, BPc), 256>>>(out);
    k_dist<<<dim3(NPCc / 256, BPc), 256>>>(pc, NPCc, out, OFF_DIST);
    k_sdist<<<dim3((PDc + 255) / 256, BPc), 256>>>(out, out);
    k_dist<<<dim3(NNSc / 256, BPc), 256>>>(ns, NNSc, out, OFF_NS);
    k_dist<<<dim3(NOUTc / 256, BPc), 256>>>(op, NOUTc, out, OFF_OUT);
    (void)in_sizes; (void)n_in; (void)out_size;
}

// round 6
// speedup vs baseline: 1.0002x; 1.0002x over previous
#include <cuda_runtime.h>
#include <math.h>

// ---------------- problem constants ----------------
#define Bc    8
#define Pc    16
#define Vc    32
#define Dc    686          // (20-2)*(39-1)+2
#define BPc   128          // B*P
#define NPCc  16384
#define NNSc  8192
#define NOUTc 8192
#define PDc   10976        // P*D

// ---------------- output offsets (tuple order, flattened) ----------------
#define OFF_OVERLAP 0                         // (B,P,P,1)     2048
#define OFF_DIST    2048                      // (B,P,NPC,1)   2097152
#define OFF_X       2099200                   // (B,P,D,3)     263424
#define OFF_SURFD   2362624                   // (B,P,P*D,1)   1404928
#define OFF_SURFP   3767552                   // (B,P*D,3)     263424
#define OFF_NS      4030976                   // (B,P,NNS,1)   1048576
#define OFF_OUT     5079552                   // (B,P,NOUT,1)  1048576
// total = 6128128

// ---------------- persistent device scratch ----------------
__device__ float  g_dirs[Dc * 3];
__device__ float  g_lv[BPc * 96];     // centered verts, [bp][coord(0..2)][v(0..31)]
__device__ float  g_tr[BPc * 3];      // mean (translation)
__device__ float  g_pe[BPc];
__device__ float  g_ipe[BPc];
__device__ float  g_scale[BPc];
__device__ float  g_nrml[BPc * Dc * 3];

// ---------------- core: soft support function ----------------
// z[v] = dot(vert_v, u);  h = (sum clip(max(z,0)/zmax)^pe)^(1/pe)
// NOTE: fmax(fmax(z,0)*k, 1e-30) == fmax(z*k, 1e-30) because k = 1/zmax > 0.
__device__ __forceinline__ float spt_core(
    const float4* __restrict__ sv,
    float pe, float ipe, float ux, float uy, float uz,
    float z[Vc], float& zmax_out)
{
    float zm = -1e30f;
#pragma unroll
    for (int v = 0; v < Vc; v++) {
        float4 w = sv[v];
        float zz = fmaf(w.x, ux, fmaf(w.y, uy, w.z * uz));
        z[v] = zz;
        zm = fmaxf(zm, zz);
    }
    zm = fminf(fmaxf(zm, 1e-30f), 1e30f);
    float k = 1.0f / zm;
    float sum = 0.0f;
#pragma unroll
    for (int v = 0; v < Vc; v++) {
        float t = fmaxf(z[v] * k, 1e-30f);
        sum += __powf(t, pe);
    }
    zmax_out = zm;
    return __powf(sum, ipe);
}

// h_out = clip(h * zmax, -1e30, 1e30)
__device__ __forceinline__ float h_clip(float h, float zm) {
    return fminf(fmaxf(h * zm, -1e30f), 1e30f);
}

// load one bp's vertex set into a float4 shared array (call with tid, then sync)
__device__ __forceinline__ void load_verts(float4* sv, int bp, int tid) {
    if (tid < Vc) {
        sv[tid] = make_float4(g_lv[bp * 96 +  0 + tid],
                              g_lv[bp * 96 + 32 + tid],
                              g_lv[bp * 96 + 64 + tid], 0.0f);
    }
}

// ---------------- kernel: directions (matches numpy linspace/cos in double) ----------------
__global__ void k_dirs() {
    int idx = blockIdx.x * blockDim.x + threadIdx.x;
    if (idx >= Dc) return;
    const double PI = 3.14159265358979323846;
    int i, j;
    if (idx < 684)      { i = idx / 38 + 1; j = idx % 38; }
    else if (idx == 684){ i = 0;  j = 0; }
    else                { i = 19; j = 0; }
    // numpy linspace: arange(n)*step + start, endpoint overwritten exactly
    double th1 = (i == 19) ? (PI / 2.0) : (-PI / 2.0 + (PI / 19.0) * (double)i);
    double th2 = -PI + (PI / 19.0) * (double)j;   // j <= 37, endpoint unused
    double c1 = cos(th1), s1 = sin(th1);
    double c2 = cos(th2), s2 = sin(th2);
    g_dirs[idx * 3 + 0] = (float)(c1 * c2);
    g_dirs[idx * 3 + 1] = (float)(c1 * s2);
    g_dirs[idx * 3 + 2] = (float)s1;
}

// ---------------- kernel: prep (mean, center, pe) ----------------
__global__ void k_prep(const float* __restrict__ verts, const float* __restrict__ smooth) {
    int bp = blockIdx.x;
    int v  = threadIdx.x;   // 32 threads
    float x = verts[(bp * Vc + v) * 3 + 0];
    float y = verts[(bp * Vc + v) * 3 + 1];
    float z = verts[(bp * Vc + v) * 3 + 2];
    float sx = x, sy = y, sz = z;
#pragma unroll
    for (int o = 16; o; o >>= 1) {
        sx += __shfl_xor_sync(0xffffffffu, sx, o);
        sy += __shfl_xor_sync(0xffffffffu, sy, o);
        sz += __shfl_xor_sync(0xffffffffu, sz, o);
    }
    float mx = sx * (1.0f / 32.0f);
    float my = sy * (1.0f / 32.0f);
    float mz = sz * (1.0f / 32.0f);
    g_lv[bp * 96 +  0 + v] = x - mx;
    g_lv[bp * 96 + 32 + v] = y - my;
    g_lv[bp * 96 + 64 + v] = z - mz;
    if (v == 0) {
        g_tr[bp * 3 + 0] = mx;
        g_tr[bp * 3 + 1] = my;
        g_tr[bp * 3 + 2] = mz;
        float pe = smooth[bp];
        g_pe[bp]  = pe;
        g_ipe[bp] = 1.0f / pe;
    }
}

// ---------------- kernel: support along DIRS + x output + scale ----------------
// 256 threads/block; each thread processes 3 directions (686 <= 3*256).
__global__ void __launch_bounds__(256) k_support(float* __restrict__ out) {
    __shared__ float4 sv[Vc];
    __shared__ float sconst[2];        // pe, ipe
    __shared__ float red[8];
    int bp  = blockIdx.x;
    int tid = threadIdx.x;
    load_verts(sv, bp, tid);
    if (tid == 0) { sconst[0] = g_pe[bp]; sconst[1] = g_ipe[bp]; }
    __syncthreads();

    float hmax = -1e30f;
    for (int d = tid; d < Dc; d += 256) {
        float ux = g_dirs[d * 3 + 0];
        float uy = g_dirs[d * 3 + 1];
        float uz = g_dirs[d * 3 + 2];
        float z[Vc], zm;
        float h = spt_core(sv, sconst[0], sconst[1], ux, uy, uz, z, zm);
        hmax = fmaxf(hmax, h_clip(h, zm));
        out[OFF_X + (bp * Dc + d) * 3 + 0] = ux;
        out[OFF_X + (bp * Dc + d) * 3 + 1] = uy;
        out[OFF_X + (bp * Dc + d) * 3 + 2] = uz;
    }
    // block max-reduce -> scale
    float m = hmax;
#pragma unroll
    for (int o = 16; o; o >>= 1) m = fmaxf(m, __shfl_xor_sync(0xffffffffu, m, o));
    if ((tid & 31) == 0) red[tid >> 5] = m;
    __syncthreads();
    if (tid == 0) {
        float mm = red[0];
#pragma unroll
        for (int w = 1; w < 8; w++) mm = fmaxf(mm, red[w]);
        g_scale[bp] = fminf(fmaxf(mm, 1e-10f), 10.0f);
    }
}

// ---------------- kernel: overlap (one block per batch) ----------------
__global__ void __launch_bounds__(256) k_overlap(float* __restrict__ out) {
    __shared__ float4 sv[Pc * Vc];
    __shared__ float st[Pc * 3];
    __shared__ float spe[Pc], sipe[Pc];
    __shared__ float sh[Pc * Pc];
    int b   = blockIdx.x;
    int tid = threadIdx.x;   // 256
    {
        int p = tid >> 4, v2 = (tid & 15) * 2;
        // each thread loads 2 vertices of hull p
        sv[p * Vc + v2 + 0] = make_float4(g_lv[(b * Pc + p) * 96 +  0 + v2],
                                          g_lv[(b * Pc + p) * 96 + 32 + v2],
                                          g_lv[(b * Pc + p) * 96 + 64 + v2], 0.0f);
        sv[p * Vc + v2 + 1] = make_float4(g_lv[(b * Pc + p) * 96 +  0 + v2 + 1],
                                          g_lv[(b * Pc + p) * 96 + 32 + v2 + 1],
                                          g_lv[(b * Pc + p) * 96 + 64 + v2 + 1], 0.0f);
    }
    if (tid < Pc * 3) st[tid] = g_tr[b * Pc * 3 + tid];
    if (tid < Pc) { spe[tid] = g_pe[b * Pc + tid]; sipe[tid] = g_ipe[b * Pc + tid]; }
    __syncthreads();

    int i = tid >> 4, j = tid & 15;
    float dx = st[j * 3 + 0] - st[i * 3 + 0];
    float dy = st[j * 3 + 1] - st[i * 3 + 1];
    float dz = st[j * 3 + 2] - st[i * 3 + 2];
    float ss = dx * dx + dy * dy + dz * dz;
    ss = fminf(fmaxf(ss, 1e-20f), 1e20f);
    float dn = sqrtf(ss);
    float ux, uy, uz;
    if (i == j) { ux = 1.0f; uy = 0.0f; uz = 0.0f; }
    else        { ux = dx / dn; uy = dy / dn; uz = dz / dn; }

    float z[Vc], zm;
    float h = spt_core(&sv[i * Vc], spe[i], sipe[i], ux, uy, uz, z, zm);
    sh[tid] = h_clip(h, zm);
    __syncthreads();

    float sep = dn - sh[i * 16 + j] - sh[j * 16 + i];
    float ov = fmaxf(-sep, 0.0f);
    if (i == j) ov = 0.0f;
    out[OFF_OVERLAP + b * 256 + i * 16 + j] = ov;
}

// ---------------- kernel: surface points + normals ----------------
// grid: (ceil(Dc/256), BPc), 256 threads
__global__ void __launch_bounds__(256) k_surf(float* __restrict__ out) {
    __shared__ float4 sv[Vc];
    __shared__ float sconst[6];   // tx,ty,tz,pe,ipe,scale
    int bp  = blockIdx.y;
    int tid = threadIdx.x;
    load_verts(sv, bp, tid);
    if (tid == 0) {
        sconst[0] = g_tr[bp * 3 + 0];
        sconst[1] = g_tr[bp * 3 + 1];
        sconst[2] = g_tr[bp * 3 + 2];
        sconst[3] = g_pe[bp];
        sconst[4] = g_ipe[bp];
        sconst[5] = g_scale[bp];
    }
    __syncthreads();
    int d = blockIdx.x * 256 + tid;
    if (d >= Dc) return;

    float sc = sconst[5];
    float dxr = g_dirs[d * 3 + 0];
    float dyr = g_dirs[d * 3 + 1];
    float dzr = g_dirs[d * 3 + 2];
    // pts = dirs*scale + trans; local = pts - trans  (replicate reference rounding)
    float px = dxr * sc + sconst[0];
    float py = dyr * sc + sconst[1];
    float pz = dzr * sc + sconst[2];
    float lx = px - sconst[0];
    float ly = py - sconst[1];
    float lz = pz - sconst[2];
    float ss = lx * lx + ly * ly + lz * lz;
    ss = fminf(fmaxf(ss, 1e-40f), 1e40f);
    float nrm = sqrtf(ss);
    float ux = lx / nrm, uy = ly / nrm, uz = lz / nrm;

    float pe = sconst[3];
    float z[Vc], zm;
    float h = spt_core(sv, pe, sconst[4], ux, uy, uz, z, zm);
    float s = fminf(fmaxf(h, 1e-30f), 1e30f);
    float rins = 1.0f / s;
    float k = 1.0f / zm;
    float pem1 = pe - 1.0f;
    float ax = 0.0f, ay = 0.0f, az = 0.0f;
#pragma unroll
    for (int v = 0; v < Vc; v++) {
        float t = fmaxf(z[v] * k, 1e-30f);
        float r = t * rins;
        float dh = fminf(fmaxf(__powf(r, pem1), 1e-30f), 1e30f);
        float4 w = sv[v];
        ax = fmaf(dh, w.x, ax);
        ay = fmaf(dh, w.y, ay);
        az = fmaf(dh, w.z, az);
    }
    int base = OFF_SURFP + (bp * Dc + d) * 3;
    out[base + 0] = ax + sconst[0];
    out[base + 1] = ay + sconst[1];
    out[base + 2] = az + sconst[2];
    g_nrml[(bp * Dc + d) * 3 + 0] = ux;
    g_nrml[(bp * Dc + d) * 3 + 1] = uy;
    g_nrml[(bp * Dc + d) * 3 + 2] = uz;
}

// ---------------- kernel: generic point-distance ----------------
__global__ void __launch_bounds__(256) k_dist(const float* __restrict__ pts, int N,
                                              float* __restrict__ out, int outoff) {
    __shared__ float4 sv[Vc];
    __shared__ float sconst[5];   // tx,ty,tz,pe,ipe
    int bp  = blockIdx.y;
    int tid = threadIdx.x;
    load_verts(sv, bp, tid);
    if (tid == 0) {
        sconst[0] = g_tr[bp * 3 + 0];
        sconst[1] = g_tr[bp * 3 + 1];
        sconst[2] = g_tr[bp * 3 + 2];
        sconst[3] = g_pe[bp];
        sconst[4] = g_ipe[bp];
    }
    __syncthreads();
    int q = blockIdx.x * blockDim.x + tid;
    if (q >= N) return;
    int b = bp >> 4;
    float px = pts[(b * N + q) * 3 + 0];
    float py = pts[(b * N + q) * 3 + 1];
    float pz = pts[(b * N + q) * 3 + 2];
    float lx = px - sconst[0];
    float ly = py - sconst[1];
    float lz = pz - sconst[2];
    float ss = lx * lx + ly * ly + lz * lz;
    ss = fminf(fmaxf(ss, 1e-40f), 1e40f);
    float nrm = sqrtf(ss);
    float ux = lx / nrm, uy = ly / nrm, uz = lz / nrm;
    float z[Vc], zm;
    float h = spt_core(sv, sconst[3], sconst[4], ux, uy, uz, z, zm);
    out[outoff + bp * N + q] = nrm - h_clip(h, zm);
}

// ---------------- kernel: surf_distance (with normal filter + diagonal) ----------------
__global__ void __launch_bounds__(256) k_sdist(const float* __restrict__ outro,
                                               float* __restrict__ out) {
    __shared__ float4 sv[Vc];
    __shared__ float st[Pc * 3];
    __shared__ float sconst[5];
    int bp  = blockIdx.y;
    int b   = bp >> 4;
    int i   = bp & 15;
    int tid = threadIdx.x;
    load_verts(sv, bp, tid);
    if (tid < Pc * 3) st[tid] = g_tr[b * Pc * 3 + tid];
    if (tid == 0) {
        sconst[0] = g_tr[bp * 3 + 0];
        sconst[1] = g_tr[bp * 3 + 1];
        sconst[2] = g_tr[bp * 3 + 2];
        sconst[3] = g_pe[bp];
        sconst[4] = g_ipe[bp];
    }
    __syncthreads();
    int n = blockIdx.x * blockDim.x + tid;
    if (n >= PDc) return;
    int j  = n / Dc;
    int dd = n - j * Dc;

    float res = 100.0f;
    bool compute = (i != j);
    if (compute) {
        float nx = g_nrml[(bp * Dc + dd) * 3 + 0];
        float ny = g_nrml[(bp * Dc + dd) * 3 + 1];
        float nz = g_nrml[(bp * Dc + dd) * 3 + 2];
        float ltx = st[j * 3 + 0] - sconst[0];
        float lty = st[j * 3 + 1] - sconst[1];
        float ltz = st[j * 3 + 2] - sconst[2];
        float nf = ltx * nx + lty * ny + ltz * nz;
        compute = !(nf < 0.0f);
    }
    if (compute) {
        float px = outro[OFF_SURFP + (b * PDc + n) * 3 + 0];
        float py = outro[OFF_SURFP + (b * PDc + n) * 3 + 1];
        float pz = outro[OFF_SURFP + (b * PDc + n) * 3 + 2];
        float lx = px - sconst[0];
        float ly = py - sconst[1];
        float lz = pz - sconst[2];
        float ss = lx * lx + ly * ly + lz * lz;
        ss = fminf(fmaxf(ss, 1e-40f), 1e40f);
        float nrm = sqrtf(ss);
        float ux = lx / nrm, uy = ly / nrm, uz = lz / nrm;
        float z[Vc], zm;
        float h = spt_core(sv, sconst[3], sconst[4], ux, uy, uz, z, zm);
        res = nrm - h_clip(h, zm);
    }
    out[OFF_SURFD + bp * PDc + n] = res;
}

// ---------------- launch ----------------
extern "C" void kernel_launch(void* const* d_in, const int* in_sizes, int n_in,
                              void* d_out, int out_size) {
    const float* verts  = (const float*)d_in[0];   // (B,P,V,3)
    const float* smooth = (const float*)d_in[1];   // (B,P)
    const float* pc     = (const float*)d_in[2];   // (B,NPC,3)
    const float* ns     = (const float*)d_in[3];   // (B,NNS,3)
    const float* op     = (const float*)d_in[4];   // (B,NOUT,3)
    float* out = (float*)d_out;

    k_dirs<<<3, 256>>>();
    k_prep<<<BPc, 32>>>(verts, smooth);
    k_support<<<BPc, 256>>>(out);
    k_overlap<<<Bc, 256>>>(out);
    k_surf<<<dim3((Dc + 255) / 256, BPc), 256>>>(out);
    k_dist<<<dim3(NPCc / 256, BPc), 256>>>(pc, NPCc, out, OFF_DIST);
    k_sdist<<<dim3((PDc + 255) / 256, BPc), 256>>>(out, out);
    k_dist<<<dim3(NNSc / 256, BPc), 256>>>(ns, NNSc, out, OFF_NS);
    k_dist<<<dim3(NOUTc / 256, BPc), 256>>>(op, NOUTc, out, OFF_OUT);
    (void)in_sizes; (void)n_in; (void)out_size;
}